// round 1
// baseline (speedup 1.0000x reference)
#include <cuda_runtime.h>

// Problem constants (fixed by the reference).
#define NN 50000
#define NE 1600000

// Scratch (device globals; no allocation allowed).
__device__ float g_h[NN * 128];     // projected features [N,128]
__device__ float g_s[NN * 4];       // alpha_src per node/head
__device__ float g_d[NN * 4];       // alpha_dst per node/head
__device__ int   g_last[NN];        // last edge index with src==n, else -1
__device__ float g_expv[NN * 4];    // exp(leaky_relu(logit)) per valid node/head
__device__ float g_sum[4];          // softmax denominators per head
__device__ float g_inv[4];          // 0.25 / g_sum

// ---------------------------------------------------------------------------
// K1: h = x @ W + b    (M=N nodes, K=128, N=128), tiled SGEMM.
// Block: 256 threads, computes 64 rows x 128 cols. BK=32.
// ---------------------------------------------------------------------------
__global__ __launch_bounds__(256) void gemm_h(const float* __restrict__ x,
                                              const float* __restrict__ W,
                                              const float* __restrict__ b,
                                              int N)
{
    __shared__ float sW[32 * 128];   // 16 KB
    __shared__ float sx[64 * 32];    // 8 KB

    const int tid  = threadIdx.x;
    const int tx   = tid & 31;       // col group: cols 4*tx .. 4*tx+3
    const int ty   = tid >> 5;       // row group: rows ty*8 .. ty*8+7
    const int row0 = blockIdx.x * 64;

    float acc[8][4];
#pragma unroll
    for (int i = 0; i < 8; i++) { acc[i][0] = acc[i][1] = acc[i][2] = acc[i][3] = 0.f; }

    for (int kk = 0; kk < 128; kk += 32) {
        // Load W tile [32][128]
        {
            int r = tid >> 5;            // 0..7
            int c = (tid & 31) * 4;
#pragma unroll
            for (int i = 0; i < 4; i++) {
                int k = kk + r + 8 * i;
                float4 wv = *reinterpret_cast<const float4*>(&W[k * 128 + c]);
                *reinterpret_cast<float4*>(&sW[(r + 8 * i) * 128 + c]) = wv;
            }
        }
        // Load x tile [64][32]
        {
            int r = tid >> 3;            // 0..31
            int c = (tid & 7) * 4;       // 0..28
#pragma unroll
            for (int i = 0; i < 2; i++) {
                int row = row0 + r + 32 * i;
                int rr  = row < N ? row : (N - 1);
                float4 xv = *reinterpret_cast<const float4*>(&x[(size_t)rr * 128 + kk + c]);
                *reinterpret_cast<float4*>(&sx[(r + 32 * i) * 32 + c]) = xv;
            }
        }
        __syncthreads();

#pragma unroll
        for (int k = 0; k < 32; k++) {
            float4 wv = *reinterpret_cast<const float4*>(&sW[k * 128 + tx * 4]);
#pragma unroll
            for (int i = 0; i < 8; i++) {
                float xv = sx[(ty * 8 + i) * 32 + k];
                acc[i][0] += xv * wv.x;
                acc[i][1] += xv * wv.y;
                acc[i][2] += xv * wv.z;
                acc[i][3] += xv * wv.w;
            }
        }
        __syncthreads();
    }

    float4 bv = *reinterpret_cast<const float4*>(&b[tx * 4]);
#pragma unroll
    for (int i = 0; i < 8; i++) {
        int row = row0 + ty * 8 + i;
        if (row < N) {
            float4 o;
            o.x = acc[i][0] + bv.x;
            o.y = acc[i][1] + bv.y;
            o.z = acc[i][2] + bv.z;
            o.w = acc[i][3] + bv.w;
            *reinterpret_cast<float4*>(&g_h[(size_t)row * 128 + tx * 4]) = o;
        }
    }
}

// ---------------------------------------------------------------------------
// K2: s[n,h] = sum_f h[n,h,f]*att_src[h,f]; d likewise. One warp per node.
// Lane l covers cols 4l..4l+3 (head = l/8); reduce over 8-lane groups.
// ---------------------------------------------------------------------------
__global__ __launch_bounds__(256) void attn_sd(const float* __restrict__ asrc,
                                               const float* __restrict__ adst,
                                               int N)
{
    int gw   = (blockIdx.x * blockDim.x + threadIdx.x) >> 5;
    int lane = threadIdx.x & 31;
    if (gw >= N) return;

    float4 hv = *reinterpret_cast<const float4*>(&g_h[(size_t)gw * 128 + lane * 4]);
    float4 as = *reinterpret_cast<const float4*>(&asrc[lane * 4]);
    float4 ad = *reinterpret_cast<const float4*>(&adst[lane * 4]);
    float ps = hv.x * as.x + hv.y * as.y + hv.z * as.z + hv.w * as.w;
    float pd = hv.x * ad.x + hv.y * ad.y + hv.z * ad.z + hv.w * ad.w;
#pragma unroll
    for (int o = 4; o > 0; o >>= 1) {
        ps += __shfl_down_sync(0xffffffffu, ps, o);
        pd += __shfl_down_sync(0xffffffffu, pd, o);
    }
    if ((lane & 7) == 0) {
        int head = lane >> 3;
        g_s[gw * 4 + head] = ps;
        g_d[gw * 4 + head] = pd;
    }
}

// ---------------------------------------------------------------------------
// K3: init: out=0, last=-1, sum=0.
// ---------------------------------------------------------------------------
__global__ void init_k(float* __restrict__ out, int N)
{
    int i = blockIdx.x * blockDim.x + threadIdx.x;
    if (i < N * 32) out[i] = 0.f;
    if (i < N)      g_last[i] = -1;
    if (i < 4)      g_sum[i] = 0.f;
}

// ---------------------------------------------------------------------------
// K4: last[src[e]] = max(e)
// ---------------------------------------------------------------------------
__global__ void last_k(const int* __restrict__ src, int E)
{
    int e = blockIdx.x * blockDim.x + threadIdx.x;
    if (e < E) atomicMax(&g_last[src[e]], e);
}

// ---------------------------------------------------------------------------
// K5: for nodes with edges: logit = leaky_relu(s[n]+d[dst[e]]+edgeMLP(e)),
// expv = exp(logit) (no max-shift needed: logits bounded ~|8|), sum-reduce.
// One thread per node.
// ---------------------------------------------------------------------------
__global__ __launch_bounds__(256) void alpha_k(const int* __restrict__ dstI,
                                               const float* __restrict__ eattr,
                                               const float* __restrict__ eW1,
                                               const float* __restrict__ eb1,
                                               const float* __restrict__ eW2,
                                               const float* __restrict__ eb2,
                                               int N)
{
    int n = blockIdx.x * blockDim.x + threadIdx.x;
    float ev[4] = {0.f, 0.f, 0.f, 0.f};
    if (n < N) {
        int e = g_last[n];
        if (e >= 0) {
            int m = dstI[e];
            float4 ea = *reinterpret_cast<const float4*>(&eattr[(size_t)e * 4]);
            float vh0 = eb2[0], vh1 = eb2[1], vh2 = eb2[2], vh3 = eb2[3];
#pragma unroll
            for (int j = 0; j < 32; j++) {
                float hid = ea.x * eW1[j] + ea.y * eW1[32 + j] +
                            ea.z * eW1[64 + j] + ea.w * eW1[96 + j] + eb1[j];
                hid = fmaxf(hid, 0.f);
                vh0 += hid * eW2[j * 4 + 0];
                vh1 += hid * eW2[j * 4 + 1];
                vh2 += hid * eW2[j * 4 + 2];
                vh3 += hid * eW2[j * 4 + 3];
            }
            float vh[4] = {vh0, vh1, vh2, vh3};
#pragma unroll
            for (int hh = 0; hh < 4; hh++) {
                float v = g_s[n * 4 + hh] + g_d[m * 4 + hh] + vh[hh];
                v = v > 0.f ? v : 0.2f * v;           // leaky_relu(0.2)
                float x = expf(v);
                ev[hh] = x;
                g_expv[n * 4 + hh] = x;
            }
        }
    }
#pragma unroll
    for (int hh = 0; hh < 4; hh++) {
        float t = ev[hh];
#pragma unroll
        for (int o = 16; o > 0; o >>= 1) t += __shfl_down_sync(0xffffffffu, t, o);
        if ((threadIdx.x & 31) == 0) atomicAdd(&g_sum[hh], t);
    }
}

// ---------------------------------------------------------------------------
// K5b: inv[h] = 0.25 / sum[h]   (0.25 = head-mean folded in)
// ---------------------------------------------------------------------------
__global__ void finalize_k()
{
    int h = threadIdx.x;
    if (h < 4) g_inv[h] = 0.25f / g_sum[h];
}

// ---------------------------------------------------------------------------
// K6: scatter. One warp per edge: out[src, f] += sum_h a_h * h[dst, h*32+f].
// ---------------------------------------------------------------------------
__global__ __launch_bounds__(256) void scatter_k(const int* __restrict__ src,
                                                 const int* __restrict__ dstI,
                                                 float* __restrict__ out,
                                                 int E)
{
    int gw   = (blockIdx.x * 256 + threadIdx.x) >> 5;
    int lane = threadIdx.x & 31;
    if (gw >= E) return;

    int n = __ldg(&src[gw]);
    int m = __ldg(&dstI[gw]);

    float a = 0.f;
    if (lane < 4) a = __ldg(&g_expv[n * 4 + lane]) * g_inv[lane];
    float a0 = __shfl_sync(0xffffffffu, a, 0);
    float a1 = __shfl_sync(0xffffffffu, a, 1);
    float a2 = __shfl_sync(0xffffffffu, a, 2);
    float a3 = __shfl_sync(0xffffffffu, a, 3);

    const float* hp = g_h + (size_t)m * 128;
    float c = a0 * __ldg(&hp[lane])      + a1 * __ldg(&hp[32 + lane]) +
              a2 * __ldg(&hp[64 + lane]) + a3 * __ldg(&hp[96 + lane]);

    atomicAdd(&out[(size_t)n * 32 + lane], c);
}

// ---------------------------------------------------------------------------
extern "C" void kernel_launch(void* const* d_in, const int* in_sizes, int n_in,
                              void* d_out, int out_size)
{
    const float* x    = (const float*)d_in[0];
    const int*   ei   = (const int*)d_in[1];
    const float* ea   = (const float*)d_in[2];
    const float* W    = (const float*)d_in[3];
    const float* b    = (const float*)d_in[4];
    const float* eW1  = (const float*)d_in[5];
    const float* eb1  = (const float*)d_in[6];
    const float* eW2  = (const float*)d_in[7];
    const float* eb2  = (const float*)d_in[8];
    const float* asrc = (const float*)d_in[9];
    const float* adst = (const float*)d_in[10];
    float* out = (float*)d_out;

    int N = in_sizes[0] / 128;
    int E = in_sizes[1] / 2;
    const int* srcI = ei;
    const int* dstI = ei + E;

    gemm_h<<<(N + 63) / 64, 256>>>(x, W, b, N);
    attn_sd<<<(N * 32 + 255) / 256, 256>>>(asrc, adst, N);
    init_k<<<(N * 32 + 255) / 256, 256>>>(out, N);
    last_k<<<(E + 255) / 256, 256>>>(srcI, E);
    alpha_k<<<(N + 255) / 256, 256>>>(dstI, ea, eW1, eb1, eW2, eb2, N);
    finalize_k<<<1, 32>>>();
    scatter_k<<<(E + 7) / 8, 256>>>(srcI, dstI, out, E);
}